// round 3
// baseline (speedup 1.0000x reference)
#include <cuda_runtime.h>

// SSIM loss — fused separable Gaussian + SSIM + device reduction.
// R3: interleaved (p,t) pairs, float4 halo loads, TY=64 tall tiles (dynamic smem),
//     8 px/thread vertical pass, symmetric packed weights.

typedef unsigned long long u64;

#define TX 32
#define TY 64
#define HALO 5
#define IN_H (TY + 2*HALO)          // 74
#define SIN_STRIDE 49               // float2 units (odd -> conflict-free LDS.64)
#define H_STRIDE 33
#define NTHREADS 256
#define IMG 512
#define TILES_X 16
#define TILES_Y 8
#define PLANES 48
#define NBLOCKS (PLANES * TILES_Y * TILES_X)   // 6144
#define NPIX 12582912.0f

#define C1 1.0e-4f
#define C2 9.0e-4f

#define N_IN (IN_H * SIN_STRIDE)    // 3626 float2
#define N_H  (IN_H * H_STRIDE)      // 2442
#define SMEM_BYTES (N_IN*8 + N_H*8 + N_H*8 + N_H*4 + 64)

__device__ float g_partials[NBLOCKS];
__device__ unsigned g_ticket = 0;

// Normalized 1D Gaussian, window=11, sigma=1.5
__device__ __forceinline__ constexpr float Wt(int k) {
    constexpr float w[11] = {
        0.00102838f, 0.00759877f, 0.03600081f, 0.10936072f, 0.21300553f,
        0.26601169f,
        0.21300553f, 0.10936072f, 0.03600081f, 0.00759877f, 0.00102838f
    };
    return w[k];
}

// ---- f32x2 packed helpers ----
__device__ __forceinline__ u64 pk(float lo, float hi) {
    u64 r; asm("mov.b64 %0, {%1, %2};" : "=l"(r) : "f"(lo), "f"(hi)); return r;
}
__device__ __forceinline__ float2 upk(u64 v) {
    float2 r; asm("mov.b64 {%0, %1}, %2;" : "=f"(r.x), "=f"(r.y) : "l"(v)); return r;
}
__device__ __forceinline__ u64 fma2(u64 a, u64 b, u64 c) {
    u64 d; asm("fma.rn.f32x2 %0, %1, %2, %3;" : "=l"(d) : "l"(a), "l"(b), "l"(c)); return d;
}
__device__ __forceinline__ u64 mul2(u64 a, u64 b) {
    u64 d; asm("mul.rn.f32x2 %0, %1, %2;" : "=l"(d) : "l"(a), "l"(b)); return d;
}

__global__ __launch_bounds__(NTHREADS, 2)
void ssim_tile_kernel(const float* __restrict__ pred,
                      const float* __restrict__ targ,
                      float* __restrict__ out) {
    extern __shared__ char raw[];
    float2* s_in  = (float2*)raw;                 // interleaved (p, t)
    float2* s_Hmu = s_in + N_IN;                  // H-blurred (mu_p, mu_t)
    float2* s_Hsq = s_Hmu + N_H;                  // H-blurred (p^2, t^2)
    float*  s_Hpt = (float*)(s_Hsq + N_H);        // H-blurred p*t
    float*  s_warp = s_Hpt + N_H;                 // [8]
    int*    s_last = (int*)(s_warp + 8);

    const int tid = threadIdx.x;
    const int ox = blockIdx.x * TX;
    const int oy = blockIdx.y * TY;
    const long plane_base = (long)blockIdx.z * (IMG * IMG);
    const float* __restrict__ p_plane = pred + plane_base;
    const float* __restrict__ t_plane = targ + plane_base;

    // symmetric packed weights: 6 distinct
    u64 w2[6];
    #pragma unroll
    for (int k = 0; k < 6; k++) w2[k] = pk(Wt(k), Wt(k));
    #define W2K(k) (w2[(k) < 6 ? (k) : 10 - (k)])

    // ---- Phase 0: vectorized halo load, interleave (p,t) ----
    // strip x in [ox-8, ox+40): 12 aligned float4 per row, 74 rows
    #pragma unroll 4
    for (int idx = tid; idx < IN_H * 12; idx += NTHREADS) {
        int r  = idx / 12;
        int c4 = idx - r * 12;
        int gy  = oy + r - HALO;
        int gx0 = ox - 8 + c4 * 4;
        float4 p4 = make_float4(0.f, 0.f, 0.f, 0.f);
        float4 t4 = p4;
        if (((unsigned)gy < IMG) & ((unsigned)gx0 < IMG)) {
            long gi = (long)gy * IMG + gx0;
            p4 = *(const float4*)(p_plane + gi);
            t4 = *(const float4*)(t_plane + gi);
        }
        float2* dst = s_in + r * SIN_STRIDE + c4 * 4;
        dst[0] = make_float2(p4.x, t4.x);
        dst[1] = make_float2(p4.y, t4.y);
        dst[2] = make_float2(p4.z, t4.z);
        dst[3] = make_float2(p4.w, t4.w);
    }
    __syncthreads();

    // ---- Phase 1: horizontal blur (8 outputs per task, row-fastest order) ----
    // tasks: 74 rows x 4 col-groups = 296
    for (int t = tid; t < IN_H * 4; t += NTHREADS) {
        int r = t % IN_H;
        int g = t / IN_H;
        int c0 = g * 8;
        const u64* src = (const u64*)(s_in + r * SIN_STRIDE + c0 + 3);

        u64 pr[18];
        #pragma unroll
        for (int i = 0; i < 18; i++) pr[i] = src[i];

        u64* dmu = (u64*)(s_Hmu + r * H_STRIDE + c0);
        u64* dsq = (u64*)(s_Hsq + r * H_STRIDE + c0);
        float* dpt = s_Hpt + r * H_STRIDE + c0;

        // pt scalars before squaring in place
        float ptv[18];
        #pragma unroll
        for (int i = 0; i < 18; i++) {
            float2 v = upk(pr[i]);
            ptv[i] = v.x * v.y;
        }

        // mu chains
        #pragma unroll
        for (int j = 0; j < 8; j++) {
            u64 a = mul2(W2K(0), pr[j]);
            #pragma unroll
            for (int k = 1; k < 11; k++) a = fma2(W2K(k), pr[j + k], a);
            dmu[j] = a;
        }
        // square in place, sq chains
        #pragma unroll
        for (int i = 0; i < 18; i++) pr[i] = mul2(pr[i], pr[i]);
        #pragma unroll
        for (int j = 0; j < 8; j++) {
            u64 a = mul2(W2K(0), pr[j]);
            #pragma unroll
            for (int k = 1; k < 11; k++) a = fma2(W2K(k), pr[j + k], a);
            dsq[j] = a;
        }
        // pt chains (scalar FFMA with immediate weights)
        #pragma unroll
        for (int j = 0; j < 8; j++) {
            float a = Wt(0) * ptv[j];
            #pragma unroll
            for (int k = 1; k < 11; k++) a = fmaf(Wt(k), ptv[j + k], a);
            dpt[j] = a;
        }
    }
    __syncthreads();

    // ---- Phase 2: vertical blur + SSIM, 8 output rows per thread ----
    const int x = tid & 31;
    const int y0 = (tid >> 5) * 8;

    u64 amu[8], asq[8];
    float apt[8];
    {
        u64 h[18];
        #pragma unroll
        for (int i = 0; i < 18; i++)
            h[i] = *(const u64*)(s_Hmu + (y0 + i) * H_STRIDE + x);
        #pragma unroll
        for (int j = 0; j < 8; j++) {
            u64 a = mul2(W2K(0), h[j]);
            #pragma unroll
            for (int k = 1; k < 11; k++) a = fma2(W2K(k), h[j + k], a);
            amu[j] = a;
        }
    }
    {
        u64 h[18];
        #pragma unroll
        for (int i = 0; i < 18; i++)
            h[i] = *(const u64*)(s_Hsq + (y0 + i) * H_STRIDE + x);
        #pragma unroll
        for (int j = 0; j < 8; j++) {
            u64 a = mul2(W2K(0), h[j]);
            #pragma unroll
            for (int k = 1; k < 11; k++) a = fma2(W2K(k), h[j + k], a);
            asq[j] = a;
        }
    }
    {
        float h[18];
        #pragma unroll
        for (int i = 0; i < 18; i++)
            h[i] = s_Hpt[(y0 + i) * H_STRIDE + x];
        #pragma unroll
        for (int j = 0; j < 8; j++) {
            float a = Wt(0) * h[j];
            #pragma unroll
            for (int k = 1; k < 11; k++) a = fmaf(Wt(k), h[j + k], a);
            apt[j] = a;
        }
    }

    float local = 0.0f;
    #pragma unroll
    for (int j = 0; j < 8; j++) {
        float2 mu = upk(amu[j]);
        float2 sq = upk(asq[j]);
        float mu_p2 = mu.x * mu.x;
        float mu_t2 = mu.y * mu.y;
        float mu_pt = mu.x * mu.y;
        float num = (2.0f * mu_pt + C1) * (2.0f * (apt[j] - mu_pt) + C2);
        float den = (mu_p2 + mu_t2 + C1) *
                    ((sq.x - mu_p2) + (sq.y - mu_t2) + C2);
        local += __fdividef(num, den);
    }

    // ---- Phase 3: block reduction ----
    float v = local;
    #pragma unroll
    for (int off = 16; off; off >>= 1)
        v += __shfl_xor_sync(0xFFFFFFFFu, v, off);
    if ((tid & 31) == 0) s_warp[tid >> 5] = v;
    __syncthreads();
    if (tid < 8) {
        v = s_warp[tid];
        #pragma unroll
        for (int off = 4; off; off >>= 1)
            v += __shfl_xor_sync(0x000000FFu, v, off);
    }
    if (tid == 0) {
        int bl = (blockIdx.z * TILES_Y + blockIdx.y) * TILES_X + blockIdx.x;
        g_partials[bl] = v;
        __threadfence();
        unsigned t = atomicInc(&g_ticket, NBLOCKS - 1);  // wraps -> self-reset
        *s_last = (t == NBLOCKS - 1);
    }
    __syncthreads();

    // ---- Phase 4: last block folds partials (fixed order, deterministic) ----
    if (*s_last) {
        float s = 0.0f;
        for (int i = tid; i < NBLOCKS; i += NTHREADS)
            s += __ldcg(&g_partials[i]);
        #pragma unroll
        for (int off = 16; off; off >>= 1)
            s += __shfl_xor_sync(0xFFFFFFFFu, s, off);
        if ((tid & 31) == 0) s_warp[tid >> 5] = s;
        __syncthreads();
        if (tid < 8) {
            s = s_warp[tid];
            #pragma unroll
            for (int off = 4; off; off >>= 1)
                s += __shfl_xor_sync(0x000000FFu, s, off);
            if (tid == 0) out[0] = 1.0f - s * (1.0f / NPIX);
        }
    }
}

extern "C" void kernel_launch(void* const* d_in, const int* in_sizes, int n_in,
                              void* d_out, int out_size) {
    const float* pred = (const float*)d_in[0];
    const float* targ = (const float*)d_in[1];
    float* out = (float*)d_out;

    cudaFuncSetAttribute(ssim_tile_kernel,
                         cudaFuncAttributeMaxDynamicSharedMemorySize, SMEM_BYTES);
    dim3 grid(TILES_X, TILES_Y, PLANES);
    ssim_tile_kernel<<<grid, NTHREADS, SMEM_BYTES>>>(pred, targ, out);
}

// round 4
// speedup vs baseline: 1.1918x; 1.1918x over previous
#include <cuda_runtime.h>

// SSIM loss — fused separable Gaussian + SSIM + device reduction.
// R4: TY=32 (static smem, 5 blocks/SM), interleaved (p,t) pairs, float4 halo
//     loads, register-scoped phase-1 to fit 51-reg cap, ticket-fused finish.

typedef unsigned long long u64;

#define TX 32
#define TY 32
#define HALO 5
#define IN_H (TY + 2*HALO)          // 42
#define SIN_STRIDE 49               // float2 units, odd -> conflict-free
#define H_STRIDE 33
#define NTHREADS 256
#define IMG 512
#define TILES_X 16
#define TILES_Y 16
#define PLANES 48
#define NBLOCKS (PLANES * TILES_Y * TILES_X)   // 12288
#define NPIX 12582912.0f

#define C1 1.0e-4f
#define C2 9.0e-4f

#define N_IN (IN_H * SIN_STRIDE)    // 2058 float2
#define N_H  (IN_H * H_STRIDE)      // 1386

__device__ float g_partials[NBLOCKS];
__device__ unsigned g_ticket = 0;

// Normalized 1D Gaussian, window=11, sigma=1.5
__device__ __forceinline__ constexpr float Wt(int k) {
    constexpr float w[11] = {
        0.00102838f, 0.00759877f, 0.03600081f, 0.10936072f, 0.21300553f,
        0.26601169f,
        0.21300553f, 0.10936072f, 0.03600081f, 0.00759877f, 0.00102838f
    };
    return w[k];
}

// ---- f32x2 packed helpers ----
__device__ __forceinline__ u64 pk(float lo, float hi) {
    u64 r; asm("mov.b64 %0, {%1, %2};" : "=l"(r) : "f"(lo), "f"(hi)); return r;
}
__device__ __forceinline__ float2 upk(u64 v) {
    float2 r; asm("mov.b64 {%0, %1}, %2;" : "=f"(r.x), "=f"(r.y) : "l"(v)); return r;
}
__device__ __forceinline__ u64 fma2(u64 a, u64 b, u64 c) {
    u64 d; asm("fma.rn.f32x2 %0, %1, %2, %3;" : "=l"(d) : "l"(a), "l"(b), "l"(c)); return d;
}
__device__ __forceinline__ u64 mul2(u64 a, u64 b) {
    u64 d; asm("mul.rn.f32x2 %0, %1, %2;" : "=l"(d) : "l"(a), "l"(b)); return d;
}

__global__ __launch_bounds__(NTHREADS, 5)
void ssim_tile_kernel(const float* __restrict__ pred,
                      const float* __restrict__ targ,
                      float* __restrict__ out) {
    __shared__ float2 s_in[N_IN];     // interleaved (p, t)
    __shared__ float2 s_Hmu[N_H];     // H-blurred (mu_p, mu_t)
    __shared__ float2 s_Hsq[N_H];     // H-blurred (p^2, t^2)
    __shared__ float  s_Hpt[N_H];     // H-blurred p*t
    __shared__ float  s_warp[8];
    __shared__ int    s_last;

    const int tid = threadIdx.x;
    const int ox = blockIdx.x * TX;
    const int oy = blockIdx.y * TY;
    const long plane_base = (long)blockIdx.z * (IMG * IMG);
    const float* __restrict__ p_plane = pred + plane_base;
    const float* __restrict__ t_plane = targ + plane_base;

    // symmetric packed weights (6 distinct)
    u64 w2[6];
    #pragma unroll
    for (int k = 0; k < 6; k++) w2[k] = pk(Wt(k), Wt(k));
    #define W2K(k) (w2[(k) < 6 ? (k) : 10 - (k)])

    // ---- Phase 0: vectorized halo load, interleave (p,t) ----
    // aligned strip x in [ox-8, ox+40): 12 float4 per row, 42 rows = 504 tasks
    #pragma unroll 2
    for (int idx = tid; idx < IN_H * 12; idx += NTHREADS) {
        int r  = idx / 12;
        int c4 = idx - r * 12;
        int gy  = oy + r - HALO;
        int gx0 = ox - 8 + c4 * 4;
        float4 p4 = make_float4(0.f, 0.f, 0.f, 0.f);
        float4 t4 = p4;
        if (((unsigned)gy < IMG) & ((unsigned)gx0 < IMG)) {
            long gi = (long)gy * IMG + gx0;
            p4 = *(const float4*)(p_plane + gi);
            t4 = *(const float4*)(t_plane + gi);
        }
        float2* dst = s_in + r * SIN_STRIDE + c4 * 4;
        dst[0] = make_float2(p4.x, t4.x);
        dst[1] = make_float2(p4.y, t4.y);
        dst[2] = make_float2(p4.z, t4.z);
        dst[3] = make_float2(p4.w, t4.w);
    }
    __syncthreads();

    // ---- Phase 1: horizontal blur, 4 outputs/task, 42*8 = 336 tasks ----
    for (int t = tid; t < IN_H * 8; t += NTHREADS) {
        int r = t % IN_H;
        int g = t / IN_H;
        int c0 = g * 4;
        const u64* src = (const u64*)(s_in + r * SIN_STRIDE + c0 + 3);
        const int hbase = r * H_STRIDE + c0;

        {   // mu and sq chains share one register window
            u64 pr[14];
            #pragma unroll
            for (int i = 0; i < 14; i++) pr[i] = src[i];

            u64* dmu = (u64*)(s_Hmu + hbase);
            #pragma unroll
            for (int j = 0; j < 4; j++) {
                u64 a = mul2(W2K(0), pr[j]);
                #pragma unroll
                for (int k = 1; k < 11; k++) a = fma2(W2K(k), pr[j + k], a);
                dmu[j] = a;
            }
            #pragma unroll
            for (int i = 0; i < 14; i++) pr[i] = mul2(pr[i], pr[i]);
            u64* dsq = (u64*)(s_Hsq + hbase);
            #pragma unroll
            for (int j = 0; j < 4; j++) {
                u64 a = mul2(W2K(0), pr[j]);
                #pragma unroll
                for (int k = 1; k < 11; k++) a = fma2(W2K(k), pr[j + k], a);
                dsq[j] = a;
            }
        }
        {   // pt chains: reload window as scalar products (small live set)
            float ptv[14];
            #pragma unroll
            for (int i = 0; i < 14; i++) {
                float2 v = upk(src[i]);
                ptv[i] = v.x * v.y;
            }
            float* dpt = s_Hpt + hbase;
            #pragma unroll
            for (int j = 0; j < 4; j++) {
                float a = Wt(0) * ptv[j];
                #pragma unroll
                for (int k = 1; k < 11; k++) a = fmaf(Wt(k), ptv[j + k], a);
                dpt[j] = a;
            }
        }
    }
    __syncthreads();

    // ---- Phase 2: vertical blur + SSIM, 4 output rows per thread ----
    const int x = tid & 31;
    const int y0 = (tid >> 5) * 4;

    u64 amu[4], asq[4];
    float apt[4];
    {
        u64 h[14];
        #pragma unroll
        for (int i = 0; i < 14; i++)
            h[i] = *(const u64*)(s_Hmu + (y0 + i) * H_STRIDE + x);
        #pragma unroll
        for (int j = 0; j < 4; j++) {
            u64 a = mul2(W2K(0), h[j]);
            #pragma unroll
            for (int k = 1; k < 11; k++) a = fma2(W2K(k), h[j + k], a);
            amu[j] = a;
        }
    }
    {
        u64 h[14];
        #pragma unroll
        for (int i = 0; i < 14; i++)
            h[i] = *(const u64*)(s_Hsq + (y0 + i) * H_STRIDE + x);
        #pragma unroll
        for (int j = 0; j < 4; j++) {
            u64 a = mul2(W2K(0), h[j]);
            #pragma unroll
            for (int k = 1; k < 11; k++) a = fma2(W2K(k), h[j + k], a);
            asq[j] = a;
        }
    }
    {
        float h[14];
        #pragma unroll
        for (int i = 0; i < 14; i++)
            h[i] = s_Hpt[(y0 + i) * H_STRIDE + x];
        #pragma unroll
        for (int j = 0; j < 4; j++) {
            float a = Wt(0) * h[j];
            #pragma unroll
            for (int k = 1; k < 11; k++) a = fmaf(Wt(k), h[j + k], a);
            apt[j] = a;
        }
    }

    float local = 0.0f;
    #pragma unroll
    for (int j = 0; j < 4; j++) {
        float2 mu = upk(amu[j]);
        float2 sq = upk(asq[j]);
        float mu_p2 = mu.x * mu.x;
        float mu_t2 = mu.y * mu.y;
        float mu_pt = mu.x * mu.y;
        float num = (2.0f * mu_pt + C1) * (2.0f * (apt[j] - mu_pt) + C2);
        float den = (mu_p2 + mu_t2 + C1) *
                    ((sq.x - mu_p2) + (sq.y - mu_t2) + C2);
        local += __fdividef(num, den);
    }

    // ---- Phase 3: block reduction ----
    float v = local;
    #pragma unroll
    for (int off = 16; off; off >>= 1)
        v += __shfl_xor_sync(0xFFFFFFFFu, v, off);
    if ((tid & 31) == 0) s_warp[tid >> 5] = v;
    __syncthreads();
    if (tid < 8) {
        v = s_warp[tid];
        #pragma unroll
        for (int off = 4; off; off >>= 1)
            v += __shfl_xor_sync(0x000000FFu, v, off);
    }
    if (tid == 0) {
        int bl = (blockIdx.z * TILES_Y + blockIdx.y) * TILES_X + blockIdx.x;
        g_partials[bl] = v;
        __threadfence();
        unsigned t = atomicInc(&g_ticket, NBLOCKS - 1);  // wraps -> self-reset
        s_last = (t == NBLOCKS - 1);
    }
    __syncthreads();

    // ---- Phase 4: last block folds partials (fixed order, deterministic) ----
    if (s_last) {
        float s = 0.0f;
        for (int i = tid; i < NBLOCKS; i += NTHREADS)
            s += __ldcg(&g_partials[i]);
        #pragma unroll
        for (int off = 16; off; off >>= 1)
            s += __shfl_xor_sync(0xFFFFFFFFu, s, off);
        if ((tid & 31) == 0) s_warp[tid >> 5] = s;
        __syncthreads();
        if (tid < 8) {
            s = s_warp[tid];
            #pragma unroll
            for (int off = 4; off; off >>= 1)
                s += __shfl_xor_sync(0x000000FFu, s, off);
            if (tid == 0) out[0] = 1.0f - s * (1.0f / NPIX);
        }
    }
}

extern "C" void kernel_launch(void* const* d_in, const int* in_sizes, int n_in,
                              void* d_out, int out_size) {
    const float* pred = (const float*)d_in[0];
    const float* targ = (const float*)d_in[1];
    float* out = (float*)d_out;

    dim3 grid(TILES_X, TILES_Y, PLANES);
    ssim_tile_kernel<<<grid, NTHREADS>>>(pred, targ, out);
}

// round 5
// speedup vs baseline: 1.2348x; 1.0361x over previous
#include <cuda_runtime.h>

// SSIM loss — fused separable Gaussian + SSIM + device reduction.
// R5: vertical-first blur (one smem read feeds mu/sq/pt), 18-window horizontal
//     pass with 8 outputs/thread, bank-exact mappings, ticket-fused finish.

typedef unsigned long long u64;

#define TX 32
#define TY 32
#define HALO 5
#define IN_H 42                     // TY + 2*HALO
#define SIN_STRIDE 49               // float2 units (odd)
#define VS 43                       // V-buffer stride (float2/float units, odd)
#define NTHREADS 256
#define IMG 512
#define TILES_X 16
#define TILES_Y 16
#define PLANES 48
#define NBLOCKS (PLANES * TILES_Y * TILES_X)   // 12288
#define NPIX 12582912.0f

#define C1 1.0e-4f
#define C2 9.0e-4f

#define N_IN (IN_H * SIN_STRIDE)    // 2058 float2
#define N_V  (TY * VS)              // 1376

__device__ float g_partials[NBLOCKS];
__device__ unsigned g_ticket = 0;

// Normalized 1D Gaussian, window=11, sigma=1.5
__device__ __forceinline__ constexpr float Wt(int k) {
    constexpr float w[11] = {
        0.00102838f, 0.00759877f, 0.03600081f, 0.10936072f, 0.21300553f,
        0.26601169f,
        0.21300553f, 0.10936072f, 0.03600081f, 0.00759877f, 0.00102838f
    };
    return w[k];
}

// ---- f32x2 packed helpers ----
__device__ __forceinline__ u64 pk(float lo, float hi) {
    u64 r; asm("mov.b64 %0, {%1, %2};" : "=l"(r) : "f"(lo), "f"(hi)); return r;
}
__device__ __forceinline__ float2 upk(u64 v) {
    float2 r; asm("mov.b64 {%0, %1}, %2;" : "=f"(r.x), "=f"(r.y) : "l"(v)); return r;
}
__device__ __forceinline__ u64 fma2(u64 a, u64 b, u64 c) {
    u64 d; asm("fma.rn.f32x2 %0, %1, %2, %3;" : "=l"(d) : "l"(a), "l"(b), "l"(c)); return d;
}
__device__ __forceinline__ u64 mul2(u64 a, u64 b) {
    u64 d; asm("mul.rn.f32x2 %0, %1, %2;" : "=l"(d) : "l"(a), "l"(b)); return d;
}

__global__ __launch_bounds__(NTHREADS, 4)
void ssim_tile_kernel(const float* __restrict__ pred,
                      const float* __restrict__ targ,
                      float* __restrict__ out) {
    __shared__ float2 s_in[N_IN];     // interleaved (p, t), rows 0..41 (y halo)
    __shared__ float2 s_Vmu[N_V];     // V-blurred (mu_p, mu_t), 32 rows x 42 cols
    __shared__ float2 s_Vsq[N_V];     // V-blurred (p^2, t^2)
    __shared__ float  s_Vpt[N_V];     // V-blurred p*t
    __shared__ float  s_warp[8];
    __shared__ int    s_last;

    const int tid = threadIdx.x;
    const int ox = blockIdx.x * TX;
    const int oy = blockIdx.y * TY;
    const long plane_base = (long)blockIdx.z * (IMG * IMG);
    const float* __restrict__ p_plane = pred + plane_base;
    const float* __restrict__ t_plane = targ + plane_base;

    // symmetric packed weights (6 distinct)
    u64 w2[6];
    #pragma unroll
    for (int k = 0; k < 6; k++) w2[k] = pk(Wt(k), Wt(k));
    #define W2K(k) (w2[(k) < 6 ? (k) : 10 - (k)])

    // ---- Phase 0: vectorized halo load, interleave (p,t) ----
    // aligned strip x in [ox-8, ox+40): 12 float4 per row, 42 rows
    #pragma unroll 2
    for (int idx = tid; idx < IN_H * 12; idx += NTHREADS) {
        int r  = idx / 12;
        int c4 = idx - r * 12;
        int gy  = oy + r - HALO;
        int gx0 = ox - 8 + c4 * 4;
        float4 p4 = make_float4(0.f, 0.f, 0.f, 0.f);
        float4 t4 = p4;
        if (((unsigned)gy < IMG) & ((unsigned)gx0 < IMG)) {
            long gi = (long)gy * IMG + gx0;
            p4 = *(const float4*)(p_plane + gi);
            t4 = *(const float4*)(t_plane + gi);
        }
        float2* dst = s_in + r * SIN_STRIDE + c4 * 4;
        dst[0] = make_float2(p4.x, t4.x);
        dst[1] = make_float2(p4.y, t4.y);
        dst[2] = make_float2(p4.z, t4.z);
        dst[3] = make_float2(p4.w, t4.w);
    }
    __syncthreads();

    // ---- Phase 1: VERTICAL blur. One smem read feeds mu/sq/pt chains. ----
    // tasks: 42 columns x 8 row-groups (4 output rows each) = 336
    for (int t = tid; t < IN_H * 8; t += NTHREADS) {
        int c = t % IN_H;           // halo-inclusive column 0..41
        int g = t / IN_H;
        int y0 = g * 4;
        const u64* colp = (const u64*)s_in + (y0 * SIN_STRIDE + c + 3);

        u64 pr[14];
        #pragma unroll
        for (int i = 0; i < 14; i++) pr[i] = colp[i * SIN_STRIDE];

        // mu chains
        u64* dmu = (u64*)s_Vmu;
        #pragma unroll
        for (int j = 0; j < 4; j++) {
            u64 a = mul2(W2K(0), pr[j]);
            #pragma unroll
            for (int k = 1; k < 11; k++) a = fma2(W2K(k), pr[j + k], a);
            dmu[(y0 + j) * VS + c] = a;
        }
        // pt chains (derive before squaring in place)
        {
            float ptv[14];
            #pragma unroll
            for (int i = 0; i < 14; i++) {
                float2 v = upk(pr[i]);
                ptv[i] = v.x * v.y;
            }
            #pragma unroll
            for (int j = 0; j < 4; j++) {
                float a = Wt(0) * ptv[j];
                #pragma unroll
                for (int k = 1; k < 11; k++) a = fmaf(Wt(k), ptv[j + k], a);
                s_Vpt[(y0 + j) * VS + c] = a;
            }
        }
        // sq chains (square in place)
        #pragma unroll
        for (int i = 0; i < 14; i++) pr[i] = mul2(pr[i], pr[i]);
        u64* dsq = (u64*)s_Vsq;
        #pragma unroll
        for (int j = 0; j < 4; j++) {
            u64 a = mul2(W2K(0), pr[j]);
            #pragma unroll
            for (int k = 1; k < 11; k++) a = fma2(W2K(k), pr[j + k], a);
            dsq[(y0 + j) * VS + c] = a;
        }
    }
    __syncthreads();

    // ---- Phase 2: HORIZONTAL blur + SSIM.
    // 128 threads: warp w handles cols 8w..8w+7, lane = row (conflict-free:
    // odd stride 43 -> 16 distinct u64 banks per 16-lane phase).
    float local = 0.0f;
    if (tid < 128) {
        const int w = tid >> 5;
        const int r = tid & 31;
        const int base = r * VS + 8 * w;

        u64 amu[8], asq[8];
        {
            u64 h[18];
            #pragma unroll
            for (int i = 0; i < 18; i++) h[i] = ((const u64*)s_Vmu)[base + i];
            #pragma unroll
            for (int j = 0; j < 8; j++) {
                u64 a = mul2(W2K(0), h[j]);
                #pragma unroll
                for (int k = 1; k < 11; k++) a = fma2(W2K(k), h[j + k], a);
                amu[j] = a;
            }
        }
        {
            u64 h[18];
            #pragma unroll
            for (int i = 0; i < 18; i++) h[i] = ((const u64*)s_Vsq)[base + i];
            #pragma unroll
            for (int j = 0; j < 8; j++) {
                u64 a = mul2(W2K(0), h[j]);
                #pragma unroll
                for (int k = 1; k < 11; k++) a = fma2(W2K(k), h[j + k], a);
                asq[j] = a;
            }
        }
        {
            float hp[18];
            #pragma unroll
            for (int i = 0; i < 18; i++) hp[i] = s_Vpt[base + i];
            #pragma unroll
            for (int j = 0; j < 8; j++) {
                float apt = Wt(0) * hp[j];
                #pragma unroll
                for (int k = 1; k < 11; k++) apt = fmaf(Wt(k), hp[j + k], apt);

                float2 mu = upk(amu[j]);
                float2 sq = upk(asq[j]);
                float mu_p2 = mu.x * mu.x;
                float mu_t2 = mu.y * mu.y;
                float mu_pt = mu.x * mu.y;
                float num = (2.0f * mu_pt + C1) * (2.0f * (apt - mu_pt) + C2);
                float den = (mu_p2 + mu_t2 + C1) *
                            ((sq.x - mu_p2) + (sq.y - mu_t2) + C2);
                local += __fdividef(num, den);
            }
        }
    }

    // ---- Phase 3: block reduction ----
    float v = local;
    #pragma unroll
    for (int off = 16; off; off >>= 1)
        v += __shfl_xor_sync(0xFFFFFFFFu, v, off);
    if ((tid & 31) == 0) s_warp[tid >> 5] = v;
    __syncthreads();
    if (tid < 8) {
        v = s_warp[tid];
        #pragma unroll
        for (int off = 4; off; off >>= 1)
            v += __shfl_xor_sync(0x000000FFu, v, off);
    }
    if (tid == 0) {
        int bl = (blockIdx.z * TILES_Y + blockIdx.y) * TILES_X + blockIdx.x;
        g_partials[bl] = v;
        __threadfence();
        unsigned t = atomicInc(&g_ticket, NBLOCKS - 1);  // wraps -> self-reset
        s_last = (t == NBLOCKS - 1);
    }
    __syncthreads();

    // ---- Phase 4: last block folds partials (fixed order, deterministic) ----
    if (s_last) {
        float s = 0.0f;
        for (int i = tid; i < NBLOCKS; i += NTHREADS)
            s += __ldcg(&g_partials[i]);
        #pragma unroll
        for (int off = 16; off; off >>= 1)
            s += __shfl_xor_sync(0xFFFFFFFFu, s, off);
        if ((tid & 31) == 0) s_warp[tid >> 5] = s;
        __syncthreads();
        if (tid < 8) {
            s = s_warp[tid];
            #pragma unroll
            for (int off = 4; off; off >>= 1)
                s += __shfl_xor_sync(0x000000FFu, s, off);
            if (tid == 0) out[0] = 1.0f - s * (1.0f / NPIX);
        }
    }
}

extern "C" void kernel_launch(void* const* d_in, const int* in_sizes, int n_in,
                              void* d_out, int out_size) {
    const float* pred = (const float*)d_in[0];
    const float* targ = (const float*)d_in[1];
    float* out = (float*)d_out;

    dim3 grid(TILES_X, TILES_Y, PLANES);
    ssim_tile_kernel<<<grid, NTHREADS>>>(pred, targ, out);
}

// round 6
// speedup vs baseline: 1.4531x; 1.1768x over previous
#include <cuda_runtime.h>

// SSIM loss — R6: two-field algebra (A=(p,t), B=(p^2+t^2, p*t)), V-pass loads
// directly from global (no staging tile), all-thread H-pass, ticket-fused finish.

typedef unsigned long long u64;

#define TX 32
#define TY 32
#define HALO 5
#define VS 43                       // V-buffer stride in u64 (odd -> conflict-free)
#define NTHREADS 256
#define IMG 512
#define TILES_X 16
#define TILES_Y 16
#define PLANES 48
#define NBLOCKS (PLANES * TILES_Y * TILES_X)   // 12288
#define NPIX 12582912.0f

#define C1 1.0e-4f
#define C2 9.0e-4f

#define N_V (TY * VS)               // 1376 u64 per buffer

__device__ float g_partials[NBLOCKS];
__device__ unsigned g_ticket = 0;

// Normalized 1D Gaussian, window=11, sigma=1.5
__device__ __forceinline__ constexpr float Wt(int k) {
    constexpr float w[11] = {
        0.00102838f, 0.00759877f, 0.03600081f, 0.10936072f, 0.21300553f,
        0.26601169f,
        0.21300553f, 0.10936072f, 0.03600081f, 0.00759877f, 0.00102838f
    };
    return w[k];
}

// ---- f32x2 packed helpers ----
__device__ __forceinline__ u64 pk(float lo, float hi) {
    u64 r; asm("mov.b64 %0, {%1, %2};" : "=l"(r) : "f"(lo), "f"(hi)); return r;
}
__device__ __forceinline__ float2 upk(u64 v) {
    float2 r; asm("mov.b64 {%0, %1}, %2;" : "=f"(r.x), "=f"(r.y) : "l"(v)); return r;
}
__device__ __forceinline__ u64 fma2(u64 a, u64 b, u64 c) {
    u64 d; asm("fma.rn.f32x2 %0, %1, %2, %3;" : "=l"(d) : "l"(a), "l"(b), "l"(c)); return d;
}
__device__ __forceinline__ u64 mul2(u64 a, u64 b) {
    u64 d; asm("mul.rn.f32x2 %0, %1, %2;" : "=l"(d) : "l"(a), "l"(b)); return d;
}

__global__ __launch_bounds__(NTHREADS, 5)
void ssim_tile_kernel(const float* __restrict__ pred,
                      const float* __restrict__ targ,
                      float* __restrict__ out) {
    __shared__ u64 s_VA[N_V];     // V-blurred (mu_p, mu_t)
    __shared__ u64 s_VB[N_V];     // V-blurred (E[p^2]+E[t^2], E[pt])
    __shared__ float s_warp[8];
    __shared__ int   s_last;

    const int tid = threadIdx.x;
    const int ox = blockIdx.x * TX;
    const int oy = blockIdx.y * TY;
    const long plane_base = (long)blockIdx.z * (IMG * IMG);
    const float* __restrict__ p_plane = pred + plane_base;
    const float* __restrict__ t_plane = targ + plane_base;

    // symmetric packed weights (6 distinct)
    u64 w2[6];
    #pragma unroll
    for (int k = 0; k < 6; k++) w2[k] = pk(Wt(k), Wt(k));
    #define W2K(k) (w2[(k) < 6 ? (k) : 10 - (k)])

    // ---- Phase 1: vertical blur straight from global.
    // 168 tasks = 42 halo-inclusive columns x 4 groups of 8 output rows.
    // 18-row register window feeds both A and B chains (one global read).
    if (tid < 168) {
        const int c = tid % 42;
        const int g = tid / 42;
        const int y0 = g * 8;
        const int gx = ox + c - HALO;
        const bool xok = (unsigned)gx < IMG;
        const int gybase = oy + y0 - HALO;

        u64 a[18];
        #pragma unroll
        for (int i = 0; i < 18; i++) {
            int gy = gybase + i;
            float pv = 0.0f, tv = 0.0f;
            if (xok & ((unsigned)gy < IMG)) {
                long o = (long)gy * IMG + gx;
                pv = __ldg(p_plane + o);
                tv = __ldg(t_plane + o);
            }
            a[i] = pk(pv, tv);
        }
        // A chains: write each output immediately (keeps live-set small)
        #pragma unroll
        for (int j = 0; j < 8; j++) {
            u64 acc = mul2(W2K(0), a[j]);
            #pragma unroll
            for (int k = 1; k < 11; k++) acc = fma2(W2K(k), a[j + k], acc);
            s_VA[(y0 + j) * VS + c] = acc;
        }
        // transform window in place: (p,t) -> (p^2+t^2, p*t)
        #pragma unroll
        for (int i = 0; i < 18; i++) {
            float2 v = upk(a[i]);
            a[i] = pk(fmaf(v.x, v.x, v.y * v.y), v.x * v.y);
        }
        #pragma unroll
        for (int j = 0; j < 8; j++) {
            u64 acc = mul2(W2K(0), a[j]);
            #pragma unroll
            for (int k = 1; k < 11; k++) acc = fma2(W2K(k), a[j + k], acc);
            s_VB[(y0 + j) * VS + c] = acc;
        }
    }
    __syncthreads();

    // ---- Phase 2: horizontal blur + SSIM. All 256 threads: 4 columns each.
    // thread (grp = tid>>5, r = tid&31): output cols 4*grp .. 4*grp+3, row r.
    const int r = tid & 31;
    const int grp = tid >> 5;
    const int base = r * VS + 4 * grp;

    float local = 0.0f;
    u64 amu[4];
    {
        u64 h[14];
        #pragma unroll
        for (int i = 0; i < 14; i++) h[i] = s_VA[base + i];
        #pragma unroll
        for (int j = 0; j < 4; j++) {
            u64 acc = mul2(W2K(0), h[j]);
            #pragma unroll
            for (int k = 1; k < 11; k++) acc = fma2(W2K(k), h[j + k], acc);
            amu[j] = acc;
        }
    }
    u64 asb[4];
    {
        u64 h[14];
        #pragma unroll
        for (int i = 0; i < 14; i++) h[i] = s_VB[base + i];
        #pragma unroll
        for (int j = 0; j < 4; j++) {
            u64 acc = mul2(W2K(0), h[j]);
            #pragma unroll
            for (int k = 1; k < 11; k++) acc = fma2(W2K(k), h[j + k], acc);
            asb[j] = acc;
        }
    }
    #pragma unroll
    for (int j = 0; j < 4; j++) {
        float2 mu = upk(amu[j]);
        float2 sb = upk(asb[j]);           // (E[p^2]+E[t^2], E[pt])
        float mu_p2 = mu.x * mu.x;
        float mu_t2 = mu.y * mu.y;
        float mu_pt = mu.x * mu.y;
        float num = (2.0f * mu_pt + C1) * (2.0f * (sb.y - mu_pt) + C2);
        float den = (mu_p2 + mu_t2 + C1) * ((sb.x - mu_p2 - mu_t2) + C2);
        local += __fdividef(num, den);
    }

    // ---- Phase 3: block reduction ----
    float v = local;
    #pragma unroll
    for (int off = 16; off; off >>= 1)
        v += __shfl_xor_sync(0xFFFFFFFFu, v, off);
    if ((tid & 31) == 0) s_warp[tid >> 5] = v;
    __syncthreads();
    if (tid < 8) {
        v = s_warp[tid];
        #pragma unroll
        for (int off = 4; off; off >>= 1)
            v += __shfl_xor_sync(0x000000FFu, v, off);
    }
    if (tid == 0) {
        int bl = (blockIdx.z * TILES_Y + blockIdx.y) * TILES_X + blockIdx.x;
        g_partials[bl] = v;
        __threadfence();
        unsigned t = atomicInc(&g_ticket, NBLOCKS - 1);  // wraps -> self-reset
        s_last = (t == NBLOCKS - 1);
    }
    __syncthreads();

    // ---- Phase 4: last block folds partials (fixed order, deterministic) ----
    if (s_last) {
        float s = 0.0f;
        for (int i = tid; i < NBLOCKS; i += NTHREADS)
            s += __ldcg(&g_partials[i]);
        #pragma unroll
        for (int off = 16; off; off >>= 1)
            s += __shfl_xor_sync(0xFFFFFFFFu, s, off);
        if ((tid & 31) == 0) s_warp[tid >> 5] = s;
        __syncthreads();
        if (tid < 8) {
            s = s_warp[tid];
            #pragma unroll
            for (int off = 4; off; off >>= 1)
                s += __shfl_xor_sync(0x000000FFu, s, off);
            if (tid == 0) out[0] = 1.0f - s * (1.0f / NPIX);
        }
    }
}

extern "C" void kernel_launch(void* const* d_in, const int* in_sizes, int n_in,
                              void* d_out, int out_size) {
    const float* pred = (const float*)d_in[0];
    const float* targ = (const float*)d_in[1];
    float* out = (float*)d_out;

    dim3 grid(TILES_X, TILES_Y, PLANES);
    ssim_tile_kernel<<<grid, NTHREADS>>>(pred, targ, out);
}

// round 7
// speedup vs baseline: 1.5810x; 1.0880x over previous
#include <cuda_runtime.h>

// SSIM loss — R7: R6 two-field algebra + interior fast-path loads (immediate-
// offset LDG, no bounds ALU) + balanced 252-task vertical pass (6 outputs/task).

typedef unsigned long long u64;

#define TX 32
#define TY 32
#define HALO 5
#define VS 43                       // V-buffer stride in u64 (odd -> conflict-free)
#define NTHREADS 256
#define IMG 512
#define TILES_X 16
#define TILES_Y 16
#define PLANES 48
#define NBLOCKS (PLANES * TILES_Y * TILES_X)   // 12288
#define NPIX 12582912.0f

#define C1 1.0e-4f
#define C2 9.0e-4f

#define N_V (TY * VS)               // 1376 u64 per buffer

__device__ float g_partials[NBLOCKS];
__device__ unsigned g_ticket = 0;

// Normalized 1D Gaussian, window=11, sigma=1.5
__device__ __forceinline__ constexpr float Wt(int k) {
    constexpr float w[11] = {
        0.00102838f, 0.00759877f, 0.03600081f, 0.10936072f, 0.21300553f,
        0.26601169f,
        0.21300553f, 0.10936072f, 0.03600081f, 0.00759877f, 0.00102838f
    };
    return w[k];
}

// ---- f32x2 packed helpers ----
__device__ __forceinline__ u64 pk(float lo, float hi) {
    u64 r; asm("mov.b64 %0, {%1, %2};" : "=l"(r) : "f"(lo), "f"(hi)); return r;
}
__device__ __forceinline__ float2 upk(u64 v) {
    float2 r; asm("mov.b64 {%0, %1}, %2;" : "=f"(r.x), "=f"(r.y) : "l"(v)); return r;
}
__device__ __forceinline__ u64 fma2(u64 a, u64 b, u64 c) {
    u64 d; asm("fma.rn.f32x2 %0, %1, %2, %3;" : "=l"(d) : "l"(a), "l"(b), "l"(c)); return d;
}
__device__ __forceinline__ u64 mul2(u64 a, u64 b) {
    u64 d; asm("mul.rn.f32x2 %0, %1, %2;" : "=l"(d) : "l"(a), "l"(b)); return d;
}

__global__ __launch_bounds__(NTHREADS, 5)
void ssim_tile_kernel(const float* __restrict__ pred,
                      const float* __restrict__ targ,
                      float* __restrict__ out) {
    __shared__ u64 s_VA[N_V];     // V-blurred (mu_p, mu_t)
    __shared__ u64 s_VB[N_V];     // V-blurred (E[p^2]+E[t^2], E[pt])
    __shared__ float s_warp[8];
    __shared__ int   s_last;

    const int tid = threadIdx.x;
    const int ox = blockIdx.x * TX;
    const int oy = blockIdx.y * TY;
    const long plane_base = (long)blockIdx.z * (IMG * IMG);
    const float* __restrict__ p_plane = pred + plane_base;
    const float* __restrict__ t_plane = targ + plane_base;

    // symmetric packed weights (6 distinct)
    u64 w2[6];
    #pragma unroll
    for (int k = 0; k < 6; k++) w2[k] = pk(Wt(k), Wt(k));
    #define W2K(k) (w2[(k) < 6 ? (k) : 10 - (k)])

    // ---- Phase 1: vertical blur from global.
    // 252 tasks = 42 halo-cols x 6 overlapping row-groups of 6 outputs
    // (y0 in {0,5,10,16,21,26}; overlapped rows write identical values).
    if (tid < 252) {
        const int c = tid % 42;
        const int g = tid / 42;
        const int y0 = 5 * g + (g > 2);
        const int gx = ox + c - HALO;
        const int gybase = oy + y0 - HALO;

        u64 a[16];
        const bool interior =
            (blockIdx.x != 0) & (blockIdx.x != TILES_X - 1) &
            (blockIdx.y != 0) & (blockIdx.y != TILES_Y - 1);

        if (interior) {
            // fast path: unconditional loads, stride folds into LDG imm offset
            const float* pp = p_plane + (long)gybase * IMG + gx;
            const float* tp = t_plane + (long)gybase * IMG + gx;
            #pragma unroll
            for (int i = 0; i < 16; i++)
                a[i] = pk(__ldg(pp + i * IMG), __ldg(tp + i * IMG));
        } else {
            const bool xok = (unsigned)gx < IMG;
            #pragma unroll
            for (int i = 0; i < 16; i++) {
                int gy = gybase + i;
                float pv = 0.0f, tv = 0.0f;
                if (xok & ((unsigned)gy < IMG)) {
                    long o = (long)gy * IMG + gx;
                    pv = __ldg(p_plane + o);
                    tv = __ldg(t_plane + o);
                }
                a[i] = pk(pv, tv);
            }
        }

        // A chains
        #pragma unroll
        for (int j = 0; j < 6; j++) {
            u64 acc = mul2(W2K(0), a[j]);
            #pragma unroll
            for (int k = 1; k < 11; k++) acc = fma2(W2K(k), a[j + k], acc);
            s_VA[(y0 + j) * VS + c] = acc;
        }
        // transform in place: (p,t) -> (p^2+t^2, p*t)
        #pragma unroll
        for (int i = 0; i < 16; i++) {
            float2 v = upk(a[i]);
            a[i] = pk(fmaf(v.x, v.x, v.y * v.y), v.x * v.y);
        }
        #pragma unroll
        for (int j = 0; j < 6; j++) {
            u64 acc = mul2(W2K(0), a[j]);
            #pragma unroll
            for (int k = 1; k < 11; k++) acc = fma2(W2K(k), a[j + k], acc);
            s_VB[(y0 + j) * VS + c] = acc;
        }
    }
    __syncthreads();

    // ---- Phase 2: horizontal blur + SSIM. 256 threads x 4 columns.
    const int r = tid & 31;
    const int grp = tid >> 5;
    const int base = r * VS + 4 * grp;

    float local = 0.0f;
    u64 amu[4];
    {
        u64 h[14];
        #pragma unroll
        for (int i = 0; i < 14; i++) h[i] = s_VA[base + i];
        #pragma unroll
        for (int j = 0; j < 4; j++) {
            u64 acc = mul2(W2K(0), h[j]);
            #pragma unroll
            for (int k = 1; k < 11; k++) acc = fma2(W2K(k), h[j + k], acc);
            amu[j] = acc;
        }
    }
    u64 asb[4];
    {
        u64 h[14];
        #pragma unroll
        for (int i = 0; i < 14; i++) h[i] = s_VB[base + i];
        #pragma unroll
        for (int j = 0; j < 4; j++) {
            u64 acc = mul2(W2K(0), h[j]);
            #pragma unroll
            for (int k = 1; k < 11; k++) acc = fma2(W2K(k), h[j + k], acc);
            asb[j] = acc;
        }
    }
    #pragma unroll
    for (int j = 0; j < 4; j++) {
        float2 mu = upk(amu[j]);
        float2 sb = upk(asb[j]);           // (E[p^2]+E[t^2], E[pt])
        float mu_p2 = mu.x * mu.x;
        float mu_t2 = mu.y * mu.y;
        float mu_pt = mu.x * mu.y;
        float num = (2.0f * mu_pt + C1) * (2.0f * (sb.y - mu_pt) + C2);
        float den = (mu_p2 + mu_t2 + C1) * ((sb.x - mu_p2 - mu_t2) + C2);
        local += __fdividef(num, den);
    }

    // ---- Phase 3: block reduction ----
    float v = local;
    #pragma unroll
    for (int off = 16; off; off >>= 1)
        v += __shfl_xor_sync(0xFFFFFFFFu, v, off);
    if ((tid & 31) == 0) s_warp[tid >> 5] = v;
    __syncthreads();
    if (tid < 8) {
        v = s_warp[tid];
        #pragma unroll
        for (int off = 4; off; off >>= 1)
            v += __shfl_xor_sync(0x000000FFu, v, off);
    }
    if (tid == 0) {
        int bl = (blockIdx.z * TILES_Y + blockIdx.y) * TILES_X + blockIdx.x;
        g_partials[bl] = v;
        __threadfence();
        unsigned t = atomicInc(&g_ticket, NBLOCKS - 1);  // wraps -> self-reset
        s_last = (t == NBLOCKS - 1);
    }
    __syncthreads();

    // ---- Phase 4: last block folds partials (fixed order, deterministic) ----
    if (s_last) {
        float s = 0.0f;
        for (int i = tid; i < NBLOCKS; i += NTHREADS)
            s += __ldcg(&g_partials[i]);
        #pragma unroll
        for (int off = 16; off; off >>= 1)
            s += __shfl_xor_sync(0xFFFFFFFFu, s, off);
        if ((tid & 31) == 0) s_warp[tid >> 5] = s;
        __syncthreads();
        if (tid < 8) {
            s = s_warp[tid];
            #pragma unroll
            for (int off = 4; off; off >>= 1)
                s += __shfl_xor_sync(0x000000FFu, s, off);
            if (tid == 0) out[0] = 1.0f - s * (1.0f / NPIX);
        }
    }
}

extern "C" void kernel_launch(void* const* d_in, const int* in_sizes, int n_in,
                              void* d_out, int out_size) {
    const float* pred = (const float*)d_in[0];
    const float* targ = (const float*)d_in[1];
    float* out = (float*)d_out;

    dim3 grid(TILES_X, TILES_Y, PLANES);
    ssim_tile_kernel<<<grid, NTHREADS>>>(pred, targ, out);
}

// round 8
// speedup vs baseline: 1.7700x; 1.1195x over previous
#include <cuda_runtime.h>

// SSIM loss — R8: 64x32 tiles (x-halo 1.16x), exact non-overlapping V-groups
// {6,6,6,6,4,4}, two-field algebra, balanced 512-task H-pass, ticket finish.

typedef unsigned long long u64;

#define TX 64
#define TY 32
#define HALO 5
#define INW 74                      // TX + 2*HALO
#define VS 75                       // V-buffer stride in u64 (odd, gcd(75,16)=1)
#define NTHREADS 256
#define IMG 512
#define TILES_X 8
#define TILES_Y 16
#define PLANES 48
#define NBLOCKS (PLANES * TILES_Y * TILES_X)   // 6144
#define NPIX 12582912.0f

#define C1 1.0e-4f
#define C2 9.0e-4f

#define N_V (TY * VS)               // 2400 u64 per buffer

__device__ float g_partials[NBLOCKS];
__device__ unsigned g_ticket = 0;

// Normalized 1D Gaussian, window=11, sigma=1.5
__device__ __forceinline__ constexpr float Wt(int k) {
    constexpr float w[11] = {
        0.00102838f, 0.00759877f, 0.03600081f, 0.10936072f, 0.21300553f,
        0.26601169f,
        0.21300553f, 0.10936072f, 0.03600081f, 0.00759877f, 0.00102838f
    };
    return w[k];
}

// ---- f32x2 packed helpers ----
__device__ __forceinline__ u64 pk(float lo, float hi) {
    u64 r; asm("mov.b64 %0, {%1, %2};" : "=l"(r) : "f"(lo), "f"(hi)); return r;
}
__device__ __forceinline__ float2 upk(u64 v) {
    float2 r; asm("mov.b64 {%0, %1}, %2;" : "=f"(r.x), "=f"(r.y) : "l"(v)); return r;
}
__device__ __forceinline__ u64 fma2(u64 a, u64 b, u64 c) {
    u64 d; asm("fma.rn.f32x2 %0, %1, %2, %3;" : "=l"(d) : "l"(a), "l"(b), "l"(c)); return d;
}
__device__ __forceinline__ u64 mul2(u64 a, u64 b) {
    u64 d; asm("mul.rn.f32x2 %0, %1, %2;" : "=l"(d) : "l"(a), "l"(b)); return d;
}
__device__ __forceinline__ u64 wsel(const u64 (&w)[6], int k) {
    return w[k < 6 ? k : 10 - k];
}

// One vertical-blur task: WIN input rows -> NOUT output rows for column c.
template<int WIN, int NOUT>
__device__ __forceinline__ void vtask(
    const float* __restrict__ p_plane, const float* __restrict__ t_plane,
    bool interior, int gx, int gybase,
    u64* __restrict__ s_VA, u64* __restrict__ s_VB,
    int y0, int c, const u64 (&w2)[6])
{
    u64 a[WIN];
    if (interior) {
        const float* pp = p_plane + (long)gybase * IMG + gx;
        const float* tp = t_plane + (long)gybase * IMG + gx;
        #pragma unroll
        for (int i = 0; i < WIN; i++)
            a[i] = pk(__ldg(pp + i * IMG), __ldg(tp + i * IMG));
    } else {
        const bool xok = (unsigned)gx < IMG;
        #pragma unroll
        for (int i = 0; i < WIN; i++) {
            int gy = gybase + i;
            float pv = 0.0f, tv = 0.0f;
            if (xok & ((unsigned)gy < IMG)) {
                long o = (long)gy * IMG + gx;
                pv = __ldg(p_plane + o);
                tv = __ldg(t_plane + o);
            }
            a[i] = pk(pv, tv);
        }
    }
    // A = (p, t) chains
    #pragma unroll
    for (int j = 0; j < NOUT; j++) {
        u64 acc = mul2(wsel(w2, 0), a[j]);
        #pragma unroll
        for (int k = 1; k < 11; k++) acc = fma2(wsel(w2, k), a[j + k], acc);
        s_VA[(y0 + j) * VS + c] = acc;
    }
    // transform in place: (p,t) -> (p^2+t^2, p*t)
    #pragma unroll
    for (int i = 0; i < WIN; i++) {
        float2 v = upk(a[i]);
        a[i] = pk(fmaf(v.x, v.x, v.y * v.y), v.x * v.y);
    }
    #pragma unroll
    for (int j = 0; j < NOUT; j++) {
        u64 acc = mul2(wsel(w2, 0), a[j]);
        #pragma unroll
        for (int k = 1; k < 11; k++) acc = fma2(wsel(w2, k), a[j + k], acc);
        s_VB[(y0 + j) * VS + c] = acc;
    }
}

__global__ __launch_bounds__(NTHREADS, 5)
void ssim_tile_kernel(const float* __restrict__ pred,
                      const float* __restrict__ targ,
                      float* __restrict__ out) {
    __shared__ u64 s_VA[N_V];     // V-blurred (mu_p, mu_t)
    __shared__ u64 s_VB[N_V];     // V-blurred (E[p^2]+E[t^2], E[pt])
    __shared__ float s_warp[8];
    __shared__ int   s_last;

    const int tid = threadIdx.x;
    const int ox = blockIdx.x * TX;
    const int oy = blockIdx.y * TY;
    const long plane_base = (long)blockIdx.z * (IMG * IMG);
    const float* __restrict__ p_plane = pred + plane_base;
    const float* __restrict__ t_plane = targ + plane_base;

    // symmetric packed weights (6 distinct)
    u64 w2[6];
    #pragma unroll
    for (int k = 0; k < 6; k++) w2[k] = pk(Wt(k), Wt(k));

    // ---- Phase 1: vertical blur from global.
    // 444 tasks = 74 halo-cols x 6 exact row-groups {6,6,6,6,4,4} (no overlap).
    const bool interior =
        (blockIdx.x != 0) & (blockIdx.x != TILES_X - 1) &
        (blockIdx.y != 0) & (blockIdx.y != TILES_Y - 1);

    #pragma unroll 1
    for (int it = 0; it < 2; it++) {
        int task = tid + it * NTHREADS;
        if (task < INW * 6) {
            int c = task % INW;
            int g = task / INW;
            int gx = ox + c - HALO;
            if (g < 4) {
                int y0 = 6 * g;
                vtask<16, 6>(p_plane, t_plane, interior, gx,
                             oy + y0 - HALO, s_VA, s_VB, y0, c, w2);
            } else {
                int y0 = 4 * g + 8;          // 24, 28
                vtask<14, 4>(p_plane, t_plane, interior, gx,
                             oy + y0 - HALO, s_VA, s_VB, y0, c, w2);
            }
        }
    }
    __syncthreads();

    // ---- Phase 2: horizontal blur + SSIM. 512 tasks of 4 cols, 2 rounds.
    float local = 0.0f;
    #pragma unroll
    for (int it = 0; it < 2; it++) {
        const int task = tid + it * NTHREADS;   // 0..511
        const int r = task & 31;
        const int grp = task >> 5;              // 0..15
        const int base = r * VS + 4 * grp;

        u64 amu[4];
        {
            u64 h[14];
            #pragma unroll
            for (int i = 0; i < 14; i++) h[i] = s_VA[base + i];
            #pragma unroll
            for (int j = 0; j < 4; j++) {
                u64 acc = mul2(wsel(w2, 0), h[j]);
                #pragma unroll
                for (int k = 1; k < 11; k++) acc = fma2(wsel(w2, k), h[j + k], acc);
                amu[j] = acc;
            }
        }
        u64 asb[4];
        {
            u64 h[14];
            #pragma unroll
            for (int i = 0; i < 14; i++) h[i] = s_VB[base + i];
            #pragma unroll
            for (int j = 0; j < 4; j++) {
                u64 acc = mul2(wsel(w2, 0), h[j]);
                #pragma unroll
                for (int k = 1; k < 11; k++) acc = fma2(wsel(w2, k), h[j + k], acc);
                asb[j] = acc;
            }
        }
        #pragma unroll
        for (int j = 0; j < 4; j++) {
            float2 mu = upk(amu[j]);
            float2 sb = upk(asb[j]);        // (E[p^2]+E[t^2], E[pt])
            float mu_p2 = mu.x * mu.x;
            float mu_t2 = mu.y * mu.y;
            float mu_pt = mu.x * mu.y;
            float num = (2.0f * mu_pt + C1) * (2.0f * (sb.y - mu_pt) + C2);
            float den = (mu_p2 + mu_t2 + C1) * ((sb.x - mu_p2 - mu_t2) + C2);
            local += __fdividef(num, den);
        }
    }

    // ---- Phase 3: block reduction ----
    float v = local;
    #pragma unroll
    for (int off = 16; off; off >>= 1)
        v += __shfl_xor_sync(0xFFFFFFFFu, v, off);
    if ((tid & 31) == 0) s_warp[tid >> 5] = v;
    __syncthreads();
    if (tid < 8) {
        v = s_warp[tid];
        #pragma unroll
        for (int off = 4; off; off >>= 1)
            v += __shfl_xor_sync(0x000000FFu, v, off);
    }
    if (tid == 0) {
        int bl = (blockIdx.z * TILES_Y + blockIdx.y) * TILES_X + blockIdx.x;
        g_partials[bl] = v;
        __threadfence();
        unsigned t = atomicInc(&g_ticket, NBLOCKS - 1);  // wraps -> self-reset
        s_last = (t == NBLOCKS - 1);
    }
    __syncthreads();

    // ---- Phase 4: last block folds partials (fixed order, deterministic) ----
    if (s_last) {
        float s = 0.0f;
        for (int i = tid; i < NBLOCKS; i += NTHREADS)
            s += __ldcg(&g_partials[i]);
        #pragma unroll
        for (int off = 16; off; off >>= 1)
            s += __shfl_xor_sync(0xFFFFFFFFu, s, off);
        if ((tid & 31) == 0) s_warp[tid >> 5] = s;
        __syncthreads();
        if (tid < 8) {
            s = s_warp[tid];
            #pragma unroll
            for (int off = 4; off; off >>= 1)
                s += __shfl_xor_sync(0x000000FFu, s, off);
            if (tid == 0) out[0] = 1.0f - s * (1.0f / NPIX);
        }
    }
}

extern "C" void kernel_launch(void* const* d_in, const int* in_sizes, int n_in,
                              void* d_out, int out_size) {
    const float* pred = (const float*)d_in[0];
    const float* targ = (const float*)d_in[1];
    float* out = (float*)d_out;

    dim3 grid(TILES_X, TILES_Y, PLANES);
    ssim_tile_kernel<<<grid, NTHREADS>>>(pred, targ, out);
}